// round 4
// baseline (speedup 1.0000x reference)
#include <cuda_runtime.h>

#define G 128
#define H 64
#define Q 32

// ---------------- constant weights ----------------
__constant__ float cW1[3*3*3*16];       // (3,3,3,1,16)
__constant__ float cW2[3*3*3*16*4];     // (3,3,3,16,4)
__constant__ float cWt1[2*2*2*4*16];    // (2,2,2,4,16)
__constant__ float cWt2[2*2*2*16];      // (2,2,2,16,1)

// ---------------- scratch (device globals; no allocs allowed) ----------------
__device__ float g_hp1[2u*64*64*64*16]; // pooled stage-1 activations, NDHWC
__device__ float g_hp2[2u*32*32*32*4];  // pooled stage-2 activations, NDHWC

__device__ __forceinline__ float frelu(float v) { return v > 0.f ? v : 0.f; }

// ============================================================================
// K1: xm = x*(occ==0); h1 = relu(conv3(xm,W1))*m0; hp1 = maxpool2(h1)
// Tile: 4^3 pooled cells = 8^3 fine voxels, halo 10^3.
// Sparse compaction: only ~10% of fine voxels are active (m0).
// ============================================================================
__global__ __launch_bounds__(256) void k1_conv1_pool(const float* __restrict__ x,
                                                     const int* __restrict__ occ)
{
    __shared__ float xs[1000];              // 10^3 masked-x halo
    __shared__ unsigned short lst[512];     // compacted active fine voxels
    __shared__ int cnt;
    __shared__ float pl[64*16];             // pooled accum [cell][ch]

    int bi  = blockIdx.x;
    int b   = bi >> 12;
    int tz  = (bi >> 8) & 15, ty = (bi >> 4) & 15, tx = bi & 15;
    int tid = threadIdx.x;

    if (tid == 0) cnt = 0;
    for (int i = tid; i < 1024; i += 256) pl[i] = 0.f;
    __syncthreads();

    int fz0 = tz*8, fy0 = ty*8, fx0 = tx*8;
    int baseb = b * (G*G*G);

    for (int i = tid; i < 1000; i += 256) {
        int z = i/100, y = (i/10)%10, xx = i%10;
        int gz = fz0+z-1, gy = fy0+y-1, gx = fx0+xx-1;
        float v = 0.f;
        bool occ0 = false;
        if ((unsigned)gz < G && (unsigned)gy < G && (unsigned)gx < G) {
            int idx = baseb + (gz*G + gy)*G + gx;
            occ0 = (occ[idx] == 0);
            if (occ0) v = x[idx];
        }
        xs[i] = v;
        // inner region of the halo -> candidate output voxel
        if (occ0 && z >= 1 && z <= 8 && y >= 1 && y <= 8 && xx >= 1 && xx <= 8) {
            int p = atomicAdd(&cnt, 1);
            lst[p] = (unsigned short)(((z-1)<<6) | ((y-1)<<3) | (xx-1));
        }
    }
    __syncthreads();

    int n = cnt;
    // 16 voxels per pass, 16 threads (=channels) per voxel
    for (int base = 0; base < n; base += 16) {
        int vi = base + (tid >> 4);
        if (vi < n) {
            int ch = tid & 15;
            int code = lst[vi];
            int lz = code >> 6, ly = (code >> 3) & 7, lx = code & 7;
            float acc = 0.f;
            #pragma unroll
            for (int dz = 0; dz < 3; dz++)
            #pragma unroll
            for (int dy = 0; dy < 3; dy++)
            #pragma unroll
            for (int dx = 0; dx < 3; dx++)
                acc = fmaf(xs[(lz+dz)*100 + (ly+dy)*10 + (lx+dx)],
                           cW1[((dz*3+dy)*3+dx)*16 + ch], acc);
            acc = frelu(acc);
            int cell = ((lz>>1)*4 + (ly>>1))*4 + (lx>>1);
            atomicMax((int*)&pl[cell*16 + ch], __float_as_int(acc)); // nonneg floats
        }
    }
    __syncthreads();

    for (int i = tid; i < 1024; i += 256) {
        int cell = i >> 4, ch = i & 15;
        int cz = cell >> 4, cy = (cell >> 2) & 3, cx = cell & 3;
        int pz = tz*4 + cz, py = ty*4 + cy, px = tx*4 + cx;
        g_hp1[(((b*H + pz)*H + py)*H + px)*16 + ch] = pl[i];
    }
}

// ============================================================================
// K2: h2 = relu(conv3(hp1,W2))*m1; hp2 = maxpool2(h2)
// Tile: 4^3 pooled cells @32^3 = 8^3 fine voxels @64^3, halo 10^3 x 16ch (64KB).
// Thread = fine voxel, 4 output-channel accumulators, float4 smem loads,
// weights via constant memory (LDCU, off the smem crossbar).
// ============================================================================
__global__ __launch_bounds__(512) void k2_conv2_pool(const int* __restrict__ occ)
{
    extern __shared__ float ts[];   // 10*10*10*16 floats = 64000 B
    __shared__ float pl[256];       // pooled accum [cell][co]

    int bi  = blockIdx.x;
    int b   = bi >> 9;
    int t   = bi & 511;
    int tz  = t >> 6, ty = (t >> 3) & 7, tx = t & 7;
    int tid = threadIdx.x;

    if (tid < 256) pl[tid] = 0.f;

    int fz0 = tz*8, fy0 = ty*8, fx0 = tx*8;

    for (int i = tid; i < 1000; i += 512) {
        int z = i/100, y = (i/10)%10, xx = i%10;
        int gz = fz0+z-1, gy = fy0+y-1, gx = fx0+xx-1;
        float4* dst = (float4*)&ts[i*16];
        if ((unsigned)gz < H && (unsigned)gy < H && (unsigned)gx < H) {
            const float4* src = (const float4*)&g_hp1[(((b*H+gz)*H + gy)*H + gx)*16];
            dst[0] = src[0]; dst[1] = src[1]; dst[2] = src[2]; dst[3] = src[3];
        } else {
            float4 zz = make_float4(0.f, 0.f, 0.f, 0.f);
            dst[0] = zz; dst[1] = zz; dst[2] = zz; dst[3] = zz;
        }
    }
    __syncthreads();

    int lz = tid >> 6, ly = (tid >> 3) & 7, lx = tid & 7;
    int uz = fz0 + lz, uy = fy0 + ly, ux = fx0 + lx;

    // m1(u) = OR over 2^3 children of (occ==0) at 128^3
    bool m1 = false;
    #pragma unroll
    for (int a = 0; a < 2; a++)
    #pragma unroll
    for (int bb = 0; bb < 2; bb++) {
        const int2 v = *(const int2*)&occ[((b*G + 2*uz + a)*G + (2*uy + bb))*G + 2*ux];
        m1 |= (v.x == 0) | (v.y == 0);
    }

    if (m1) {
        float a0 = 0.f, a1 = 0.f, a2 = 0.f, a3 = 0.f;
        #pragma unroll 1
        for (int dz = 0; dz < 3; dz++) {
            #pragma unroll 1
            for (int dy = 0; dy < 3; dy++) {
                #pragma unroll
                for (int dx = 0; dx < 3; dx++) {
                    const float* ip = &ts[((lz+dz)*100 + (ly+dy)*10 + (lx+dx))*16];
                    const float* wp = &cW2[((dz*3+dy)*3+dx)*64];
                    #pragma unroll
                    for (int cq = 0; cq < 4; cq++) {
                        float4 v = *(const float4*)(ip + cq*4);
                        const float* w = wp + cq*16;
                        a0 = fmaf(v.x, w[ 0], a0); a1 = fmaf(v.x, w[ 1], a1);
                        a2 = fmaf(v.x, w[ 2], a2); a3 = fmaf(v.x, w[ 3], a3);
                        a0 = fmaf(v.y, w[ 4], a0); a1 = fmaf(v.y, w[ 5], a1);
                        a2 = fmaf(v.y, w[ 6], a2); a3 = fmaf(v.y, w[ 7], a3);
                        a0 = fmaf(v.z, w[ 8], a0); a1 = fmaf(v.z, w[ 9], a1);
                        a2 = fmaf(v.z, w[10], a2); a3 = fmaf(v.z, w[11], a3);
                        a0 = fmaf(v.w, w[12], a0); a1 = fmaf(v.w, w[13], a1);
                        a2 = fmaf(v.w, w[14], a2); a3 = fmaf(v.w, w[15], a3);
                    }
                }
            }
        }
        int cell = ((lz>>1)*4 + (ly>>1))*4 + (lx>>1);
        atomicMax((int*)&pl[cell*4 + 0], __float_as_int(frelu(a0)));
        atomicMax((int*)&pl[cell*4 + 1], __float_as_int(frelu(a1)));
        atomicMax((int*)&pl[cell*4 + 2], __float_as_int(frelu(a2)));
        atomicMax((int*)&pl[cell*4 + 3], __float_as_int(frelu(a3)));
    }
    __syncthreads();

    if (tid < 256) {
        int cell = tid >> 2, co = tid & 3;
        int cz = cell >> 4, cy = (cell >> 2) & 3, cx = cell & 3;
        int pz = tz*4 + cz, py = ty*4 + cy, px = tx*4 + cx;
        g_hp2[(((b*Q + pz)*Q + py)*Q + px)*4 + co] = pl[tid];
    }
}

// ============================================================================
// K3: fused decoder. Per 32^3 cell i:
//   m3/m4 inside the 4^3 output block all equal m2(i).
//   h3(2i+d,co) = relu(sum_ci hp2(i,ci)*Wt1[1-d][ci][co])   (JAX conv_transpose flip)
//   out(2u+e)   = sigmoid(sum_co h3(u,co)*Wt2[1-e][co]) * m
// ============================================================================
__global__ __launch_bounds__(256) void k3_tconv(const int* __restrict__ occ,
                                                float* __restrict__ out)
{
    int gid = blockIdx.x*256 + threadIdx.x;
    int b  = gid >> 15;
    int c  = gid & 32767;
    int iz = c >> 10, iy = (c >> 5) & 31, ix = c & 31;

    // m2(i) = OR over 4^3 block of (occ==0) at 128^3
    bool m2 = false;
    #pragma unroll
    for (int a = 0; a < 4; a++)
    #pragma unroll
    for (int bb = 0; bb < 4; bb++) {
        const int4 v = *(const int4*)&occ[((b*G + 4*iz + a)*G + (4*iy + bb))*G + 4*ix];
        m2 |= (v.x == 0) | (v.y == 0) | (v.z == 0) | (v.w == 0);
    }

    float ov[64];
    #pragma unroll
    for (int i = 0; i < 64; i++) ov[i] = 0.f;

    if (m2) {
        const float4 hin = *(const float4*)&g_hp2[gid*4];
        #pragma unroll
        for (int dz = 0; dz < 2; dz++)
        #pragma unroll
        for (int dy = 0; dy < 2; dy++)
        #pragma unroll
        for (int dx = 0; dx < 2; dx++) {
            const float* w1p = &cWt1[(((1-dz)*2 + (1-dy))*2 + (1-dx))*64];
            float h3[16];
            #pragma unroll
            for (int co = 0; co < 16; co++) {
                float v = fmaf(hin.x, w1p[co],
                          fmaf(hin.y, w1p[16+co],
                          fmaf(hin.z, w1p[32+co], hin.w * w1p[48+co])));
                h3[co] = v > 0.f ? v : 0.f;
            }
            #pragma unroll
            for (int ez = 0; ez < 2; ez++)
            #pragma unroll
            for (int ey = 0; ey < 2; ey++)
            #pragma unroll
            for (int ex = 0; ex < 2; ex++) {
                const float* w2p = &cWt2[(((1-ez)*2 + (1-ey))*2 + (1-ex))*16];
                float s = 0.f;
                #pragma unroll
                for (int co = 0; co < 16; co++) s = fmaf(h3[co], w2p[co], s);
                s = 1.f / (1.f + __expf(-s));
                ov[((2*dz+ez)*4 + (2*dy+ey))*4 + (2*dx+ex)] = s;
            }
        }
    }

    #pragma unroll
    for (int r = 0; r < 16; r++) {
        int wz = r >> 2, wy = r & 3;
        *(float4*)&out[((b*G + 4*iz + wz)*G + (4*iy + wy))*G + 4*ix] =
            *(float4*)&ov[r*4];
    }
}

// ============================================================================
extern "C" void kernel_launch(void* const* d_in, const int* in_sizes, int n_in,
                              void* d_out, int out_size)
{
    const float* x   = (const float*)d_in[0];
    const float* W1  = (const float*)d_in[1];
    const float* W2  = (const float*)d_in[2];
    const float* Wt1 = (const float*)d_in[3];
    const float* Wt2 = (const float*)d_in[4];
    const int*   occ = (const int*)  d_in[5];

    int B = in_sizes[0] / (G*G*G);

    cudaMemcpyToSymbolAsync(cW1,  W1,  3*3*3*16*sizeof(float),   0, cudaMemcpyDeviceToDevice, 0);
    cudaMemcpyToSymbolAsync(cW2,  W2,  3*3*3*16*4*sizeof(float), 0, cudaMemcpyDeviceToDevice, 0);
    cudaMemcpyToSymbolAsync(cWt1, Wt1, 2*2*2*4*16*sizeof(float), 0, cudaMemcpyDeviceToDevice, 0);
    cudaMemcpyToSymbolAsync(cWt2, Wt2, 2*2*2*16*sizeof(float),   0, cudaMemcpyDeviceToDevice, 0);

    cudaFuncSetAttribute(k2_conv2_pool, cudaFuncAttributeMaxDynamicSharedMemorySize, 64000);

    k1_conv1_pool<<<B*4096, 256>>>(x, occ);
    k2_conv2_pool<<<B*512, 512, 64000>>>(occ);
    k3_tconv<<<B*128, 256>>>(occ, (float*)d_out);
}

// round 5
// speedup vs baseline: 4.0620x; 4.0620x over previous
#include <cuda_runtime.h>

#define G 128
#define H 64
#define Q 32

// ---------------- constant weights (uniform-access only!) ----------------
__constant__ float cW2[3*3*3*16*4];     // (3,3,3,16,4)
__constant__ float cWt1[2*2*2*4*16];    // (2,2,2,4,16)
__constant__ float cWt2[2*2*2*16];      // (2,2,2,16,1)

// ---------------- scratch (device globals; no allocs allowed) ----------------
__device__ float g_hp1[2u*64*64*64*16]; // pooled stage-1 activations, NDHWC
__device__ float g_hp2[2u*32*32*32*4];  // pooled stage-2 activations, NDHWC

__device__ __forceinline__ float frelu(float v) { return v > 0.f ? v : 0.f; }
__device__ __forceinline__ float fsig(float v) { return 1.f / (1.f + __expf(-v)); }

// ============================================================================
// K1: xm = x*(occ==0); h1 = relu(conv3(xm,W1))*m0; hp1 = maxpool2(h1)
// Tile: 4^3 pooled cells = 8^3 fine voxels, halo 10^3.
// Thread group = 16 threads (lane = out channel) per pooled cell.
// Weights live in REGISTERS (27 per thread, its channel's taps) -> no
// divergent constant loads, no shared atomics, 2 barriers.
// ============================================================================
__global__ __launch_bounds__(256) void k1_conv1_pool(const float* __restrict__ x,
                                                     const int* __restrict__ occ,
                                                     const float* __restrict__ W1)
{
    __shared__ float xs[1000];              // 10^3 masked-x halo
    __shared__ unsigned char msk[512];      // m0 for inner 8^3

    int bi  = blockIdx.x;
    int b   = bi >> 12;
    int tz  = (bi >> 8) & 15, ty = (bi >> 4) & 15, tx = bi & 15;
    int tid = threadIdx.x;
    int ch  = tid & 15;
    int g   = tid >> 4;

    // per-thread weights for this thread's output channel (W1: [tap][1][16])
    float w[27];
    #pragma unroll
    for (int t = 0; t < 27; t++) w[t] = W1[t*16 + ch];

    int fz0 = tz*8, fy0 = ty*8, fx0 = tx*8;
    int baseb = b * (G*G*G);

    #pragma unroll
    for (int it = 0; it < 4; it++) {
        int i = tid + it*256;
        if (i < 1000) {
            int z = i/100, y = (i/10)%10, xx = i%10;
            int gz = fz0+z-1, gy = fy0+y-1, gx = fx0+xx-1;
            float v = 0.f;
            int   o = 1;
            bool inb = ((unsigned)gz < G) & ((unsigned)gy < G) & ((unsigned)gx < G);
            if (inb) {
                int idx = baseb + (gz*G + gy)*G + gx;
                o = occ[idx];          // two independent loads, no dependence
                v = x[idx];
            }
            bool act = inb && (o == 0);
            xs[i] = act ? v : 0.f;
            if (z >= 1 && z <= 8 && y >= 1 && y <= 8 && xx >= 1 && xx <= 8)
                msk[((z-1)<<6) | ((y-1)<<3) | (xx-1)] = (unsigned char)act;
        }
    }
    __syncthreads();

    // 16 groups x 4 cells each = 64 pooled cells
    for (int cc = g; cc < 64; cc += 16) {
        int cz = cc >> 4, cy = (cc >> 2) & 3, cx = cc & 3;
        float mv = 0.f;     // relu floor folded into the max
        for (int k = 0; k < 8; k++) {
            int lz = cz*2 + ((k>>2)&1);
            int ly = cy*2 + ((k>>1)&1);
            int lx = cx*2 + (k&1);
            if (msk[(lz<<6) | (ly<<3) | lx]) {
                float acc = 0.f;
                #pragma unroll
                for (int dz = 0; dz < 3; dz++)
                #pragma unroll
                for (int dy = 0; dy < 3; dy++)
                #pragma unroll
                for (int dx = 0; dx < 3; dx++)
                    acc = fmaf(xs[(lz+dz)*100 + (ly+dy)*10 + (lx+dx)],
                               w[(dz*3+dy)*3+dx], acc);
                mv = fmaxf(mv, acc);
            }
        }
        int pz = tz*4 + cz, py = ty*4 + cy, px = tx*4 + cx;
        g_hp1[((((b*H + pz)*H + py)*H + px) << 4) + ch] = mv;
    }
}

// ============================================================================
// K2: h2 = relu(conv3(hp1,W2))*m1; hp2 = maxpool2(h2)
// Tile: 8^3 fine voxels @64^3, halo 10^3 x 16ch (64KB dynamic smem).
// Thread = fine voxel, 4 output-channel accumulators; weights via constant
// memory with UNIFORM addresses (outer taps kept as runtime loop).
// Pooling via smem staging + explicit reduce (no atomics).
// ============================================================================
__global__ __launch_bounds__(512) void k2_conv2_pool(const int* __restrict__ occ)
{
    extern __shared__ float ts[];       // 10*10*10*16 floats = 64000 B
    __shared__ float hs[512*4];         // per-voxel relu'd masked outputs

    int bi  = blockIdx.x;
    int b   = bi >> 9;
    int t   = bi & 511;
    int tz  = t >> 6, ty = (t >> 3) & 7, tx = t & 7;
    int tid = threadIdx.x;

    int fz0 = tz*8, fy0 = ty*8, fx0 = tx*8;

    for (int i = tid; i < 1000; i += 512) {
        int z = i/100, y = (i/10)%10, xx = i%10;
        int gz = fz0+z-1, gy = fy0+y-1, gx = fx0+xx-1;
        float4* dst = (float4*)&ts[i*16];
        if ((unsigned)gz < H && (unsigned)gy < H && (unsigned)gx < H) {
            const float4* src = (const float4*)&g_hp1[(((b*H+gz)*H + gy)*H + gx)*16];
            dst[0] = src[0]; dst[1] = src[1]; dst[2] = src[2]; dst[3] = src[3];
        } else {
            float4 zz = make_float4(0.f, 0.f, 0.f, 0.f);
            dst[0] = zz; dst[1] = zz; dst[2] = zz; dst[3] = zz;
        }
    }
    __syncthreads();

    int lz = tid >> 6, ly = (tid >> 3) & 7, lx = tid & 7;
    int uz = fz0 + lz, uy = fy0 + ly, ux = fx0 + lx;

    // m1(u) = OR over 2^3 children of (occ==0) at 128^3
    bool m1 = false;
    #pragma unroll
    for (int a = 0; a < 2; a++)
    #pragma unroll
    for (int bb = 0; bb < 2; bb++) {
        const int2 v = *(const int2*)&occ[((b*G + 2*uz + a)*G + (2*uy + bb))*G + 2*ux];
        m1 |= (v.x == 0) | (v.y == 0);
    }

    float a0 = 0.f, a1 = 0.f, a2 = 0.f, a3 = 0.f;
    if (m1) {
        #pragma unroll 1
        for (int dz = 0; dz < 3; dz++) {
            #pragma unroll 1
            for (int dy = 0; dy < 3; dy++) {
                #pragma unroll
                for (int dx = 0; dx < 3; dx++) {
                    const float* ip = &ts[((lz+dz)*100 + (ly+dy)*10 + (lx+dx))*16];
                    const float* wp = &cW2[((dz*3+dy)*3+dx)*64];
                    #pragma unroll
                    for (int cq = 0; cq < 4; cq++) {
                        float4 v = *(const float4*)(ip + cq*4);
                        const float* w = wp + cq*16;
                        a0 = fmaf(v.x, w[ 0], a0); a1 = fmaf(v.x, w[ 1], a1);
                        a2 = fmaf(v.x, w[ 2], a2); a3 = fmaf(v.x, w[ 3], a3);
                        a0 = fmaf(v.y, w[ 4], a0); a1 = fmaf(v.y, w[ 5], a1);
                        a2 = fmaf(v.y, w[ 6], a2); a3 = fmaf(v.y, w[ 7], a3);
                        a0 = fmaf(v.z, w[ 8], a0); a1 = fmaf(v.z, w[ 9], a1);
                        a2 = fmaf(v.z, w[10], a2); a3 = fmaf(v.z, w[11], a3);
                        a0 = fmaf(v.w, w[12], a0); a1 = fmaf(v.w, w[13], a1);
                        a2 = fmaf(v.w, w[14], a2); a3 = fmaf(v.w, w[15], a3);
                    }
                }
            }
        }
        a0 = frelu(a0); a1 = frelu(a1); a2 = frelu(a2); a3 = frelu(a3);
    }
    float4* hv = (float4*)&hs[tid*4];
    *hv = make_float4(a0, a1, a2, a3);
    __syncthreads();

    if (tid < 256) {
        int cell = tid >> 2, co = tid & 3;
        int cz = cell >> 4, cy = (cell >> 2) & 3, cx = cell & 3;
        float mv = 0.f;
        #pragma unroll
        for (int k = 0; k < 8; k++) {
            int child = (((cz*2 + ((k>>2)&1)) << 6) |
                         ((cy*2 + ((k>>1)&1)) << 3) |
                          (cx*2 + (k&1)));
            mv = fmaxf(mv, hs[child*4 + co]);
        }
        int pz = tz*4 + cz, py = ty*4 + cy, px = tx*4 + cx;
        g_hp2[(((b*Q + pz)*Q + py)*Q + px)*4 + co] = mv;
    }
}

// ============================================================================
// K3: fused decoder, no local-memory staging (direct float4 stores).
// Per 32^3 cell i, m3/m4 inside the 4^3 output block all equal m2(i).
//   h3(2i+d,co) = relu(sum_ci hp2(i,ci)*Wt1[1-d][ci][co])   (conv_transpose flip)
//   out(2u+e)   = sigmoid(sum_co h3(u,co)*Wt2[1-e][co]) * m
// ============================================================================
__global__ __launch_bounds__(256) void k3_tconv(const int* __restrict__ occ,
                                                float* __restrict__ out)
{
    int gid = blockIdx.x*256 + threadIdx.x;
    int b  = gid >> 15;
    int c  = gid & 32767;
    int iz = c >> 10, iy = (c >> 5) & 31, ix = c & 31;

    // m2(i) = OR over 4^3 block of (occ==0) at 128^3
    bool m2 = false;
    #pragma unroll
    for (int a = 0; a < 4; a++)
    #pragma unroll
    for (int bb = 0; bb < 4; bb++) {
        const int4 v = *(const int4*)&occ[((b*G + 4*iz + a)*G + (4*iy + bb))*G + 4*ix];
        m2 |= (v.x == 0) | (v.y == 0) | (v.z == 0) | (v.w == 0);
    }

    int obase = ((b*G + 4*iz)*G + 4*iy)*G + 4*ix;

    if (!m2) {
        float4 zz = make_float4(0.f, 0.f, 0.f, 0.f);
        #pragma unroll
        for (int r = 0; r < 16; r++) {
            int wz = r >> 2, wy = r & 3;
            *(float4*)&out[obase + (wz*G + wy)*G] = zz;
        }
        return;
    }

    const float4 hin = *(const float4*)&g_hp2[gid*4];

    #pragma unroll
    for (int dz = 0; dz < 2; dz++)
    #pragma unroll
    for (int dy = 0; dy < 2; dy++) {
        // h3 for dx=0 and dx=1 (kernel index flipped: 1-d)
        float h3a[16], h3b[16];
        {
            const float* wA = &cWt1[(((1-dz)*2 + (1-dy))*2 + 1)*64]; // dx=0
            const float* wB = &cWt1[(((1-dz)*2 + (1-dy))*2 + 0)*64]; // dx=1
            #pragma unroll
            for (int co = 0; co < 16; co++) {
                float va = fmaf(hin.x, wA[co],
                           fmaf(hin.y, wA[16+co],
                           fmaf(hin.z, wA[32+co], hin.w * wA[48+co])));
                float vb = fmaf(hin.x, wB[co],
                           fmaf(hin.y, wB[16+co],
                           fmaf(hin.z, wB[32+co], hin.w * wB[48+co])));
                h3a[co] = frelu(va);
                h3b[co] = frelu(vb);
            }
        }
        #pragma unroll
        for (int ez = 0; ez < 2; ez++)
        #pragma unroll
        for (int ey = 0; ey < 2; ey++) {
            const float* w2e0 = &cWt2[((((1-ez)*2 + (1-ey))*2) + 1)*16]; // ex=0
            const float* w2e1 = &cWt2[((((1-ez)*2 + (1-ey))*2) + 0)*16]; // ex=1
            float sx = 0.f, sy = 0.f, sz = 0.f, sw = 0.f;
            #pragma unroll
            for (int co = 0; co < 16; co++) {
                sx = fmaf(h3a[co], w2e0[co], sx);
                sy = fmaf(h3a[co], w2e1[co], sy);
                sz = fmaf(h3b[co], w2e0[co], sz);
                sw = fmaf(h3b[co], w2e1[co], sw);
            }
            float4 o = make_float4(fsig(sx), fsig(sy), fsig(sz), fsig(sw));
            int wz = 2*dz + ez, wy = 2*dy + ey;
            *(float4*)&out[obase + (wz*G + wy)*G] = o;
        }
    }
}

// ============================================================================
extern "C" void kernel_launch(void* const* d_in, const int* in_sizes, int n_in,
                              void* d_out, int out_size)
{
    const float* x   = (const float*)d_in[0];
    const float* W1  = (const float*)d_in[1];
    const float* W2  = (const float*)d_in[2];
    const float* Wt1 = (const float*)d_in[3];
    const float* Wt2 = (const float*)d_in[4];
    const int*   occ = (const int*)  d_in[5];

    int B = in_sizes[0] / (G*G*G);

    cudaMemcpyToSymbolAsync(cW2,  W2,  3*3*3*16*4*sizeof(float), 0, cudaMemcpyDeviceToDevice, 0);
    cudaMemcpyToSymbolAsync(cWt1, Wt1, 2*2*2*4*16*sizeof(float), 0, cudaMemcpyDeviceToDevice, 0);
    cudaMemcpyToSymbolAsync(cWt2, Wt2, 2*2*2*16*sizeof(float),   0, cudaMemcpyDeviceToDevice, 0);

    cudaFuncSetAttribute(k2_conv2_pool, cudaFuncAttributeMaxDynamicSharedMemorySize, 64000);

    k1_conv1_pool<<<B*4096, 256>>>(x, occ, W1);
    k2_conv2_pool<<<B*512, 512, 64000>>>(occ);
    k3_tconv<<<B*128, 256>>>(occ, (float*)d_out);
}